// round 9
// baseline (speedup 1.0000x reference)
#include <cuda_runtime.h>
#include <cstdint>

// Problem constants: B=1, Z=1, X=Y=360, C=80, Np=1,993,728
#define XDIM  360
#define YDIM  360
#define CDIM  80
#define CELLS (XDIM * YDIM)          // 129600 = 16200 * 8
#define NP_MAX 2000000
#define SCAN_NB 127                  // ceil(129600/1024), <= 148 SMs (all resident)

__device__ __align__(256) int g_cell[NP_MAX];      // cell per point, -1 dropped
__device__ __align__(256) int g_count[CELLS];      // histogram (zeroed by gather)
__device__ __align__(256) int g_offset[CELLS];     // exclusive scan
__device__ __align__(256) int g_cursor[CELLS];     // reorder cursors
__device__ __align__(256) int g_pid[NP_MAX];       // point ids sorted by cell
__device__ int g_ready[SCAN_NB];                   // lookback flags, zeroed by idx_hist

// ---------------------------------------------------------------------------
// 1) cell index + histogram. Also re-zeroes g_ready for this replay's scan.
// XLA rewrites (v-lo)/DX into (v-lo)*(1/DX) with rn-rounded f32 reciprocal —
// replicate exactly (validated: rel_err ~6e-8).
// ---------------------------------------------------------------------------
__global__ void idx_hist_kernel(const float* __restrict__ geom, int np) {
    if (blockIdx.x == 0 && threadIdx.x < SCAN_NB)
        g_ready[threadIdx.x] = 0;

    int p = blockIdx.x * blockDim.x + threadIdx.x;
    if (p >= np) return;

    float gx = geom[3 * (size_t)p + 0];
    float gy = geom[3 * (size_t)p + 1];
    float gz = geom[3 * (size_t)p + 2];

    const float lox = -53.85f - 0.3f * 0.5f;   // -54.0f in f32
    const float loz =   0.0f  - 20.0f * 0.5f;  // -10.0f
    const float rxy = 1.0f / 0.3f;             // rn f32 reciprocal
    const float rz  = 1.0f / 20.0f;            // exact

    int xi = (int)floorf((gx - lox) * rxy);
    int yi = (int)floorf((gy - lox) * rxy);
    int zi = (int)floorf((gz - loz) * rz);

    bool kept = (xi >= 0) & (xi < XDIM) & (yi >= 0) & (yi < YDIM) &
                (zi >= 0) & (zi < 1);
    int cell = kept ? (xi * YDIM + yi) : -1;
    g_cell[p] = cell;
    if (cell >= 0) atomicAdd(&g_count[cell], 1);
}

// ---------------------------------------------------------------------------
// 2) single-kernel exclusive scan with decoupled lookback (127 blocks, all
// resident in wave 1). g_ready pre-zeroed by idx_hist.
// ---------------------------------------------------------------------------
__global__ __launch_bounds__(1024) void scan_kernel() {
    __shared__ int warpsum[32];
    __shared__ int sbase;

    int t = threadIdx.x;
    int b = blockIdx.x;
    int gid = b * 1024 + t;
    int v = (gid < CELLS) ? g_count[gid] : 0;

    int x = v;
    #pragma unroll
    for (int d = 1; d < 32; d <<= 1) {
        int y = __shfl_up_sync(0xFFFFFFFFu, x, d);
        if ((t & 31) >= d) x += y;
    }
    if ((t & 31) == 31) warpsum[t >> 5] = x;
    __syncthreads();
    if (t < 32) {
        int w = warpsum[t];
        #pragma unroll
        for (int d = 1; d < 32; d <<= 1) {
            int y = __shfl_up_sync(0xFFFFFFFFu, w, d);
            if (t >= d) w += y;
        }
        warpsum[t] = w;
    }
    __syncthreads();
    int wbase = (t >= 32) ? warpsum[(t >> 5) - 1] : 0;
    int incl = x + wbase;

    if (t == 1023) {
        atomicExch(&g_ready[b], incl + 1);   // publish aggregate (+1 = ready)
    }

    if (t < 32) {
        int sum = 0;
        for (int j = t; j < b; j += 32) {
            int r;
            do { r = *(volatile int*)&g_ready[j]; } while (r == 0);
            sum += r - 1;
        }
        #pragma unroll
        for (int d = 16; d >= 1; d >>= 1)
            sum += __shfl_xor_sync(0xFFFFFFFFu, sum, d);
        if (t == 0) sbase = sum;
    }
    __syncthreads();

    if (gid < CELLS) {
        int o = incl - v + sbase;            // exclusive prefix
        g_offset[gid] = o;
        g_cursor[gid] = o;
    }
}

// ---------------------------------------------------------------------------
// 3) reorder: bucket point ids by cell
// ---------------------------------------------------------------------------
__global__ void reorder_kernel(int np) {
    int p = blockIdx.x * blockDim.x + threadIdx.x;
    if (p >= np) return;
    int cell = g_cell[p];
    if (cell < 0) return;
    int pos = atomicAdd(&g_cursor[cell], 1);
    g_pid[pos] = p;
}

// ---------------------------------------------------------------------------
// 4) gather: warp per cell; lanes 0..19 own one float4 of C=80.
//    MLP-first design (R8 lesson: regs beat occupancy): 256-thread blocks,
//    NO min-blocks clause -> ptxas free to allocate ~70-90 regs -> 8 pids +
//    8 float4 rows genuinely in flight per warp. ~3 blocks/SM = 24 warps
//    each with MLP~8 (192 point-rows outstanding/SM vs 12 in R8).
//    Epilogue transposes via smem; zeroes g_count for next replay.
// ---------------------------------------------------------------------------
__global__ __launch_bounds__(256) void gather_kernel(
    const float* __restrict__ feats, float* __restrict__ out)
{
    __shared__ float s[8][81];    // [local cell][channel], stride 81

    int lane = threadIdx.x & 31;
    int wid  = threadIdx.x >> 5;            // local cell 0..7
    int cell = blockIdx.x * 8 + wid;        // CELLS = 16200*8 exact

    int start = g_offset[cell];
    int cnt   = g_count[cell];
    if (lane == 0) g_count[cell] = 0;       // reset for next replay

    const float4* __restrict__ f4 = reinterpret_cast<const float4*>(feats);

    if (lane < 20) {
        float4 acc = make_float4(0.f, 0.f, 0.f, 0.f);
        int k = 0;

        // 8-wide batches: 8 independent pid loads, then 8 independent LDG.128
        for (; k + 8 <= cnt; k += 8) {
            int p[8];
            #pragma unroll
            for (int j = 0; j < 8; j++) p[j] = g_pid[start + k + j];
            float4 v[8];
            #pragma unroll
            for (int j = 0; j < 8; j++) v[j] = f4[(size_t)p[j] * 20 + lane];
            #pragma unroll
            for (int j = 0; j < 8; j++) {
                acc.x += v[j].x; acc.y += v[j].y;
                acc.z += v[j].z; acc.w += v[j].w;
            }
        }
        // 4-wide batch
        if (k + 4 <= cnt) {
            int p[4];
            #pragma unroll
            for (int j = 0; j < 4; j++) p[j] = g_pid[start + k + j];
            float4 v[4];
            #pragma unroll
            for (int j = 0; j < 4; j++) v[j] = f4[(size_t)p[j] * 20 + lane];
            #pragma unroll
            for (int j = 0; j < 4; j++) {
                acc.x += v[j].x; acc.y += v[j].y;
                acc.z += v[j].z; acc.w += v[j].w;
            }
            k += 4;
        }
        // scalar tail
        for (; k < cnt; k++) {
            int p0 = g_pid[start + k];
            float4 v0 = f4[(size_t)p0 * 20 + lane];
            acc.x += v0.x; acc.y += v0.y; acc.z += v0.z; acc.w += v0.w;
        }

        int c = 4 * lane;
        s[wid][c + 0] = acc.x;
        s[wid][c + 1] = acc.y;
        s[wid][c + 2] = acc.z;
        s[wid][c + 3] = acc.w;
    }
    __syncthreads();

    // write out: 80 c x 8 xy = 640 floats per block
    int xy0 = blockIdx.x * 8;
    #pragma unroll
    for (int r = 0; r < 3; r++) {
        int linear = r * 256 + threadIdx.x;
        if (linear < CDIM * 8) {
            int c = linear >> 3;          // channel
            int x = linear & 7;           // local xy
            out[(size_t)c * CELLS + xy0 + x] = s[x][c];
        }
    }
}

// ---------------------------------------------------------------------------
// Launch (4 kernels)
// ---------------------------------------------------------------------------
extern "C" void kernel_launch(void* const* d_in, const int* in_sizes, int n_in,
                              void* d_out, int out_size)
{
    const float* geom  = (const float*)d_in[0];
    const float* feats = (const float*)d_in[1];
    float* out = (float*)d_out;

    int np = in_sizes[0] / 3;   // 1,993,728

    idx_hist_kernel<<<(np + 255) / 256, 256>>>(geom, np);
    scan_kernel<<<SCAN_NB, 1024>>>();
    reorder_kernel<<<(np + 255) / 256, 256>>>(np);
    gather_kernel<<<CELLS / 8, 256>>>(feats, out);
}

// round 10
// speedup vs baseline: 1.5416x; 1.5416x over previous
#include <cuda_runtime.h>
#include <cstdint>

// Problem constants: B=1, Z=1, X=Y=360, C=80, Np=1,993,728
#define XDIM  360
#define YDIM  360
#define CDIM  80
#define CELLS (XDIM * YDIM)          // 129600 = 16200 * 8
#define NP_MAX 2000000
#define SCAN_NB 127                  // ceil(129600/1024), <= 148 SMs
#define BATCH 8                      // points per cp.async batch

__device__ __align__(256) int g_cell[NP_MAX];      // cell per point, -1 dropped
__device__ __align__(256) int g_count[CELLS];      // histogram (zeroed by gather)
__device__ __align__(256) int g_offset[CELLS];     // exclusive scan
__device__ __align__(256) int g_cursor[CELLS];     // reorder cursors
__device__ __align__(256) int g_pid[NP_MAX];       // point ids sorted by cell
__device__ int g_ready[SCAN_NB];                   // lookback flags, zeroed by idx_hist

// ---------------------------------------------------------------------------
// 1) cell index + histogram. Also re-zeroes g_ready for this replay's scan.
// XLA reciprocal-multiply binning (validated: rel_err ~6e-8).
// ---------------------------------------------------------------------------
__global__ void idx_hist_kernel(const float* __restrict__ geom, int np) {
    if (blockIdx.x == 0 && threadIdx.x < SCAN_NB)
        g_ready[threadIdx.x] = 0;

    int p = blockIdx.x * blockDim.x + threadIdx.x;
    if (p >= np) return;

    float gx = geom[3 * (size_t)p + 0];
    float gy = geom[3 * (size_t)p + 1];
    float gz = geom[3 * (size_t)p + 2];

    const float lox = -53.85f - 0.3f * 0.5f;   // -54.0f in f32
    const float loz =   0.0f  - 20.0f * 0.5f;  // -10.0f
    const float rxy = 1.0f / 0.3f;             // rn f32 reciprocal
    const float rz  = 1.0f / 20.0f;            // exact

    int xi = (int)floorf((gx - lox) * rxy);
    int yi = (int)floorf((gy - lox) * rxy);
    int zi = (int)floorf((gz - loz) * rz);

    bool kept = (xi >= 0) & (xi < XDIM) & (yi >= 0) & (yi < YDIM) &
                (zi >= 0) & (zi < 1);
    int cell = kept ? (xi * YDIM + yi) : -1;
    g_cell[p] = cell;
    if (cell >= 0) atomicAdd(&g_count[cell], 1);
}

// ---------------------------------------------------------------------------
// 2) single-kernel exclusive scan with decoupled lookback (127 blocks).
// ---------------------------------------------------------------------------
__global__ __launch_bounds__(1024) void scan_kernel() {
    __shared__ int warpsum[32];
    __shared__ int sbase;

    int t = threadIdx.x;
    int b = blockIdx.x;
    int gid = b * 1024 + t;
    int v = (gid < CELLS) ? g_count[gid] : 0;

    int x = v;
    #pragma unroll
    for (int d = 1; d < 32; d <<= 1) {
        int y = __shfl_up_sync(0xFFFFFFFFu, x, d);
        if ((t & 31) >= d) x += y;
    }
    if ((t & 31) == 31) warpsum[t >> 5] = x;
    __syncthreads();
    if (t < 32) {
        int w = warpsum[t];
        #pragma unroll
        for (int d = 1; d < 32; d <<= 1) {
            int y = __shfl_up_sync(0xFFFFFFFFu, w, d);
            if (t >= d) w += y;
        }
        warpsum[t] = w;
    }
    __syncthreads();
    int wbase = (t >= 32) ? warpsum[(t >> 5) - 1] : 0;
    int incl = x + wbase;

    if (t == 1023) {
        atomicExch(&g_ready[b], incl + 1);   // publish aggregate (+1 = ready)
    }

    if (t < 32) {
        int sum = 0;
        for (int j = t; j < b; j += 32) {
            int r;
            do { r = *(volatile int*)&g_ready[j]; } while (r == 0);
            sum += r - 1;
        }
        #pragma unroll
        for (int d = 16; d >= 1; d >>= 1)
            sum += __shfl_xor_sync(0xFFFFFFFFu, sum, d);
        if (t == 0) sbase = sum;
    }
    __syncthreads();

    if (gid < CELLS) {
        int o = incl - v + sbase;            // exclusive prefix
        g_offset[gid] = o;
        g_cursor[gid] = o;
    }
}

// ---------------------------------------------------------------------------
// 3) reorder: bucket point ids by cell
// ---------------------------------------------------------------------------
__global__ void reorder_kernel(int np) {
    int p = blockIdx.x * blockDim.x + threadIdx.x;
    if (p >= np) return;
    int cell = g_cell[p];
    if (cell < 0) return;
    int pos = atomicAdd(&g_cursor[cell], 1);
    g_pid[pos] = p;
}

// ---------------------------------------------------------------------------
// 4) gather with cp.async double buffering.
//    R9 lesson: ptxas will NOT keep 8 LDG.128 results live in registers —
//    use LDGSTS (zero register cost, HW-guaranteed concurrency). Warp per
//    cell, BATCH=8 points staged per buffer (2.5KB), 2 buffers. Per SM:
//    5 blocks x 8 warps x 8 rows = 320 rows (100KB) outstanding.
// ---------------------------------------------------------------------------
__device__ __forceinline__ void cp16(float4* dst_smem, const float4* src) {
    uint32_t d = (uint32_t)__cvta_generic_to_shared(dst_smem);
    asm volatile("cp.async.cg.shared.global [%0], [%1], 16;"
                 :: "r"(d), "l"(src) : "memory");
}
__device__ __forceinline__ void cp_commit() {
    asm volatile("cp.async.commit_group;" ::: "memory");
}

__global__ __launch_bounds__(256) void gather_kernel(
    const float* __restrict__ feats, float* __restrict__ out)
{
    __shared__ float4 sbuf[8][2][BATCH * 20];   // 40 KB staging
    __shared__ float  s[8][81];                 // out tile

    int lane = threadIdx.x & 31;
    int wid  = threadIdx.x >> 5;            // local cell 0..7
    int cell = blockIdx.x * 8 + wid;        // CELLS = 16200*8 exact

    int start = g_offset[cell];
    int cnt   = g_count[cell];
    if (lane == 0) g_count[cell] = 0;       // reset for next replay

    const float4* __restrict__ f4 = reinterpret_cast<const float4*>(feats);
    float4 acc = make_float4(0.f, 0.f, 0.f, 0.f);

    if (cnt > 0) {
        int buf = 0;
        int k = 0;
        // ---- prologue: issue batch 0 into buf 0
        int n0 = (cnt < BATCH) ? cnt : BATCH;
        {
            int pidreg = (lane < n0) ? g_pid[start + lane] : 0;
            int nch = n0 * 20;
            int niter = (nch + 31) >> 5;
            for (int i = 0; i < niter; i++) {
                int c = i * 32 + lane;
                int j = c / 20;
                int sub = c - j * 20;
                int p = __shfl_sync(0xFFFFFFFFu, pidreg, j & 7);
                if (c < nch)
                    cp16(&sbuf[wid][0][c], f4 + (size_t)p * 20 + sub);
            }
            cp_commit();
        }
        k = n0;

        // ---- main loop: issue next batch, wait+accumulate current
        while (k < cnt) {
            int n1 = cnt - k; if (n1 > BATCH) n1 = BATCH;
            int pidreg = (lane < n1) ? g_pid[start + k + lane] : 0;
            int nch = n1 * 20;
            int niter = (nch + 31) >> 5;
            int nb = buf ^ 1;
            for (int i = 0; i < niter; i++) {
                int c = i * 32 + lane;
                int j = c / 20;
                int sub = c - j * 20;
                int p = __shfl_sync(0xFFFFFFFFu, pidreg, j & 7);
                if (c < nch)
                    cp16(&sbuf[wid][nb][c], f4 + (size_t)p * 20 + sub);
            }
            cp_commit();

            asm volatile("cp.async.wait_group 1;" ::: "memory");
            __syncwarp();
            if (lane < 20) {
                for (int j = 0; j < n0; j++) {
                    float4 v = sbuf[wid][buf][j * 20 + lane];
                    acc.x += v.x; acc.y += v.y; acc.z += v.z; acc.w += v.w;
                }
            }
            __syncwarp();      // reads done before this buffer is refilled
            buf = nb;
            n0 = n1;
            k += n1;
        }

        // ---- epilogue: drain last batch
        asm volatile("cp.async.wait_group 0;" ::: "memory");
        __syncwarp();
        if (lane < 20) {
            for (int j = 0; j < n0; j++) {
                float4 v = sbuf[wid][buf][j * 20 + lane];
                acc.x += v.x; acc.y += v.y; acc.z += v.z; acc.w += v.w;
            }
        }
    }

    if (lane < 20) {
        int c = 4 * lane;
        s[wid][c + 0] = acc.x;
        s[wid][c + 1] = acc.y;
        s[wid][c + 2] = acc.z;
        s[wid][c + 3] = acc.w;
    }
    __syncthreads();

    // write out: 80 c x 8 xy = 640 floats per block
    int xy0 = blockIdx.x * 8;
    #pragma unroll
    for (int r = 0; r < 3; r++) {
        int linear = r * 256 + threadIdx.x;
        if (linear < CDIM * 8) {
            int c = linear >> 3;          // channel
            int x = linear & 7;           // local xy
            out[(size_t)c * CELLS + xy0 + x] = s[x][c];
        }
    }
}

// ---------------------------------------------------------------------------
// Launch (4 kernels)
// ---------------------------------------------------------------------------
extern "C" void kernel_launch(void* const* d_in, const int* in_sizes, int n_in,
                              void* d_out, int out_size)
{
    const float* geom  = (const float*)d_in[0];
    const float* feats = (const float*)d_in[1];
    float* out = (float*)d_out;

    int np = in_sizes[0] / 3;   // 1,993,728

    idx_hist_kernel<<<(np + 255) / 256, 256>>>(geom, np);
    scan_kernel<<<SCAN_NB, 1024>>>();
    reorder_kernel<<<(np + 255) / 256, 256>>>(np);
    gather_kernel<<<CELLS / 8, 256>>>(feats, out);
}